// round 15
// baseline (speedup 1.0000x reference)
#include <cuda_runtime.h>
#include <cuda_bf16.h>
#include <cstdint>
#include <math.h>

// Fixed shapes: B=4096, D=512, V=50000
#define D      512
#define EPS    1e-8f
#define NEGINF -1e30f
#define BM 128
#define BN 128
#define BK 64
#define MAXB   4096
#define MAXV   50048
#define MAXNC  400

// -------- device-global scratch (no allocations allowed) --------
__device__ __nv_bfloat16 g_inn_bf16[MAXB * D];   // normalized input, bf16 (4 MB)
__device__ __nv_bfloat16 g_vnn_bf16[MAXV * D];   // normalized veclist, bf16 (~51 MB)
__device__ float g_dpos[MAXB];
__device__ float g_cval[MAXB * MAXNC * 2];
__device__ int   g_cidx[MAXB * MAXNC * 2];
__device__ int   g_sel [MAXB * 2];

__device__ __forceinline__ uint32_t smem_u32(const void* p) {
    uint32_t a;
    asm("{ .reg .u64 t; cvta.to.shared.u64 t, %1; cvt.u32.u64 %0, t; }" : "=r"(a) : "l"(p));
    return a;
}
#define SW128(off) ((off) ^ (((off) >> 3) & 0x70))

#define CP_ASYNC16(dst, src) \
    asm volatile("cp.async.cg.shared.global [%0], [%1], 16;" :: "r"(dst), "l"(src))
#define CP_ASYNC16_ZFILL(dst, src, sz) \
    asm volatile("cp.async.cg.shared.global [%0], [%1], 16, %2;" :: "r"(dst), "l"(src), "r"(sz))
#define CP_COMMIT()  asm volatile("cp.async.commit_group;" ::: "memory")
#define CP_WAIT(n)   asm volatile("cp.async.wait_group %0;" :: "n"(n) : "memory")

#define LDMX4(r0, r1, r2, r3, addr) \
    asm volatile("ldmatrix.sync.aligned.m8n8.x4.shared.b16 {%0,%1,%2,%3}, [%4];" \
                 : "=r"(r0), "=r"(r1), "=r"(r2), "=r"(r3) : "r"(addr))

#define MMA16816(d, a, b0, b1) \
    asm volatile("mma.sync.aligned.m16n8k16.row.col.f32.bf16.bf16.f32 " \
                 "{%0,%1,%2,%3}, {%4,%5,%6,%7}, {%8,%9}, {%0,%1,%2,%3};" \
                 : "+f"((d)[0]), "+f"((d)[1]), "+f"((d)[2]), "+f"((d)[3]) \
                 : "r"((a)[0]), "r"((a)[1]), "r"((a)[2]), "r"((a)[3]), \
                   "r"(b0), "r"(b1))

__device__ __forceinline__ float warpSum(float v) {
#pragma unroll
    for (int o = 16; o > 0; o >>= 1) v += __shfl_down_sync(0xffffffffu, v, o);
    return v;
}

// ---------------- prep: normalize input rows -> bf16, compute d_pos ----------------
__global__ void prep_input_kernel(const float* __restrict__ in,
                                  const float* __restrict__ tgt) {
    __shared__ float sbuf[3][4];
    int b = blockIdx.x, t = threadIdx.x;  // 128 threads
    const float4* ip = (const float4*)(in  + (size_t)b * D);
    const float4* tp = (const float4*)(tgt + (size_t)b * D);
    float4 iv = ip[t], tv = tp[t];
    float ii = iv.x*iv.x + iv.y*iv.y + iv.z*iv.z + iv.w*iv.w;
    float tt = tv.x*tv.x + tv.y*tv.y + tv.z*tv.z + tv.w*tv.w;
    float it = iv.x*tv.x + iv.y*tv.y + iv.z*tv.z + iv.w*tv.w;
    ii = warpSum(ii); tt = warpSum(tt); it = warpSum(it);
    int w = t >> 5, l = t & 31;
    if (l == 0) { sbuf[0][w] = ii; sbuf[1][w] = tt; sbuf[2][w] = it; }
    __syncthreads();
    float s_ii = sbuf[0][0]+sbuf[0][1]+sbuf[0][2]+sbuf[0][3];
    float s_tt = sbuf[1][0]+sbuf[1][1]+sbuf[1][2]+sbuf[1][3];
    float s_it = sbuf[2][0]+sbuf[2][1]+sbuf[2][2]+sbuf[2][3];
    float ni = fmaxf(sqrtf(s_ii), EPS);
    float inv = 1.0f / ni;
    __nv_bfloat162* op = (__nv_bfloat162*)(g_inn_bf16 + (size_t)b * D);
    op[t*2]   = __floats2bfloat162_rn(iv.x*inv, iv.y*inv);
    op[t*2+1] = __floats2bfloat162_rn(iv.z*inv, iv.w*inv);
    if (t == 0) {
        float nt  = fmaxf(sqrtf(s_tt), EPS);
        float sim = s_it / (ni * nt);
        g_dpos[b] = sqrtf(fmaxf(2.0f * (1.0f - sim), 1e-12f));
    }
}

// ---------------- prep: normalize veclist rows -> bf16 ----------------
__global__ void prep_vec_kernel(const float* __restrict__ vl, int V) {
    __shared__ float sbuf[4];
    int v = blockIdx.x;
    if (v >= V) return;
    int t = threadIdx.x;  // 128 threads
    const float4* vp = (const float4*)(vl + (size_t)v * D);
    float4 x = vp[t];
    float nn = x.x*x.x + x.y*x.y + x.z*x.z + x.w*x.w;
    nn = warpSum(nn);
    int w = t >> 5, l = t & 31;
    if (l == 0) sbuf[w] = nn;
    __syncthreads();
    float s = sbuf[0]+sbuf[1]+sbuf[2]+sbuf[3];
    float inv = 1.0f / fmaxf(sqrtf(s), EPS);
    __nv_bfloat162* op = (__nv_bfloat162*)(g_vnn_bf16 + (size_t)v * D);
    op[t*2]   = __floats2bfloat162_rn(x.x*inv, x.y*inv);
    op[t*2+1] = __floats2bfloat162_rn(x.z*inv, x.w*inv);
}

// ---------------- HMMA GEMM + fused per-tile top-2 (packed keys) ----------------
// key = (float_bits(sim) & ~0x7F) | local_col(7b). Ranking via float fmax/fmin on
// keys (2^-16 relative truncation — far below bf16 compute noise). Index rides in
// the low mantissa bits; unpacked at the end into the g_cval/g_cidx interface.

// dynamic SMEM layout (72 KB):
//   A bufs: 2 x 16 KB at 0, 16384      (128 rows x 64 bf16, SW128)
//   B bufs: 2 x 16 KB at 32768, 49152  (128 rows x 64 bf16, SW128)
//   sc[8][128] uint2 key pairs at 65536 (8 KB, dedicated — no aliasing)
#define TILE_B     16384
#define OFF_SC     65536
#define SMEM_BYTES (65536 + 8192)

template <bool MASK>
__device__ __forceinline__ void epilogue_topk(const float (&acc)[4][8][4],
                                              uint2 (*sc)[128],
                                              const uint32_t (&colc)[8][2],
                                              int wm, int l, int n0, int V, int qidx) {
#pragma unroll
    for (int mt = 0; mt < 4; mt++) {
#pragma unroll
        for (int h = 0; h < 2; h++) {
            int lrow = wm * 64 + mt * 16 + h * 8 + (l >> 2);
            float hi[8], lo[8];
#pragma unroll
            for (int nt = 0; nt < 8; nt++) {
                uint32_t kb0 = (__float_as_uint(acc[mt][nt][h*2+0]) & 0xFFFFFF80u) | colc[nt][0];
                uint32_t kb1 = (__float_as_uint(acc[mt][nt][h*2+1]) & 0xFFFFFF80u) | colc[nt][1];
                float f0 = __uint_as_float(kb0);
                float f1 = __uint_as_float(kb1);
                if (MASK) {
                    if (n0 + (int)colc[nt][0] >= V) f0 = NEGINF;
                    if (n0 + (int)colc[nt][1] >= V) f1 = NEGINF;
                }
                hi[nt] = fmaxf(f0, f1);
                lo[nt] = fminf(f0, f1);
            }
            // tournament 8 -> 1 (independent subtrees, FMNMX only)
#pragma unroll
            for (int s = 1; s < 8; s <<= 1)
#pragma unroll
                for (int i = 0; i < 8; i += 2 * s) {
                    float mn = fminf(hi[i], hi[i + s]);
                    hi[i] = fmaxf(hi[i], hi[i + s]);
                    lo[i] = fmaxf(mn, fmaxf(lo[i], lo[i + s]));
                }
            sc[qidx][lrow] = make_uint2(__float_as_uint(hi[0]), __float_as_uint(lo[0]));
        }
    }
}

__global__ void __launch_bounds__(128, 2)
gemm_hmma_kernel(int V, int NC, int NT) {
    extern __shared__ __align__(1024) char smem[];
    const uint32_t sb = smem_u32(smem);
    uint2 (*sc)[128] = reinterpret_cast<uint2 (*)[128]>(smem + OFF_SC);

    const int tid = threadIdx.x;          // 128 threads, 4 warps
    const int w   = tid >> 5, l = tid & 31;
    const int wm  = w & 1;                // M half: rows wm*64 .. +63
    const int wn  = w >> 1;               // N half: cols wn*64 .. +63

    // ---- cp.async addressing state (reset per tile) ----
    const int r0 = tid >> 3, cu = tid & 7;
    const uint32_t dof0 = SW128((uint32_t)(r0 * 128 + cu * 16));
    const char* pA;
    const char* pB[8];
    uint32_t    szB[8];

    auto setup_ptrs = [&](int m0, int n0) {
        pA = (const char*)g_inn_bf16 + (size_t)(m0 + r0) * (D * 2) + cu * 16;
#pragma unroll
        for (int i = 0; i < 8; i++) {
            int vr = n0 + r0 + 16 * i;
            int vrc = vr < V ? vr : (V - 1);
            pB[i] = (const char*)g_vnn_bf16 + (size_t)vrc * (D * 2) + cu * 16;
            szB[i] = (vr < V) ? 16u : 0u;
        }
    };
    auto load_chunk = [&](int buf) {
        const uint32_t da = sb + buf * TILE_B;
        const uint32_t db = sb + 32768 + buf * TILE_B;
#pragma unroll
        for (int i = 0; i < 8; i++) CP_ASYNC16(da + dof0 + i * 2048, pA + i * 16384);
#pragma unroll
        for (int i = 0; i < 8; i++) CP_ASYNC16_ZFILL(db + dof0 + i * 2048, pB[i], szB[i]);
        CP_COMMIT();
        pA += 128;
#pragma unroll
        for (int i = 0; i < 8; i++) pB[i] += 128;
    };

    // ---- hoisted ldmatrix addressing ----
    const int lrow16 = l & 15, khalf = (l >> 4) * 16;
    const uint32_t xorv = (uint32_t)((lrow16 & 7) << 4);
    uint32_t koff[4];
#pragma unroll
    for (int ks = 0; ks < 4; ks++) koff[ks] = ((uint32_t)(ks * 32 + khalf)) ^ xorv;
    uint32_t aRow[4], bRow[4];
#pragma unroll
    for (int mt = 0; mt < 4; mt++) aRow[mt] = (uint32_t)((wm * 64 + mt * 16 + lrow16) * 128);
#pragma unroll
    for (int np = 0; np < 4; np++) bRow[np] = (uint32_t)((wn * 64 + np * 16 + lrow16) * 128);

    // ---- hoisted epilogue column codes (7-bit local cols) ----
    uint32_t colc[8][2];
#pragma unroll
    for (int nt = 0; nt < 8; nt++) {
        colc[nt][0] = (uint32_t)(wn * 64 + nt * 8 + 2 * (l & 3));
        colc[nt][1] = colc[nt][0] + 1;
    }
    const int qidx = wn * 4 + (l & 3);    // 0..7

    // ---- persistent tile loop ----
    int t = blockIdx.x;
    if (t < NT) {
        setup_ptrs((t / NC) * BM, (t % NC) * BN);
        load_chunk(0);
    }

    uint32_t afr[2][4][4], bfr[2][4][4];

    for (; t < NT; t += gridDim.x) {
        const int by = t / NC, bx = t % NC;
        const int m0 = by * BM, n0 = bx * BN;
        const int tn = t + (int)gridDim.x;

        float acc[4][8][4];
#pragma unroll
        for (int i = 0; i < 4; i++)
#pragma unroll
            for (int j = 0; j < 8; j++)
#pragma unroll
                for (int q = 0; q < 4; q++) acc[i][j][q] = 0.0f;

#pragma unroll 1
        for (int ck = 0; ck < 8; ck++) {
            const int buf = ck & 1;
            if (ck < 7) {
                load_chunk(buf ^ 1); CP_WAIT(1);
            } else if (tn < NT) {
                // prefetch NEXT TILE's chunk 0 — its latency hides under the epilogue
                setup_ptrs((tn / NC) * BM, (tn % NC) * BN);
                load_chunk(buf ^ 1); CP_WAIT(1);
            } else {
                CP_WAIT(0);
            }
            __syncthreads();

            const uint32_t aBase = sb + buf * TILE_B;
            const uint32_t bBase = sb + 32768 + buf * TILE_B;

            // prefetch ks=0 fragments
#pragma unroll
            for (int mt = 0; mt < 4; mt++)
                LDMX4(afr[0][mt][0], afr[0][mt][1], afr[0][mt][2], afr[0][mt][3],
                      aBase + aRow[mt] + koff[0]);
#pragma unroll
            for (int np = 0; np < 4; np++)
                LDMX4(bfr[0][np][0], bfr[0][np][1], bfr[0][np][2], bfr[0][np][3],
                      bBase + bRow[np] + koff[0]);

#pragma unroll
            for (int ks = 0; ks < 4; ks++) {
                const int cur = ks & 1, nxt = cur ^ 1;
                if (ks < 3) {
#pragma unroll
                    for (int mt = 0; mt < 4; mt++)
                        LDMX4(afr[nxt][mt][0], afr[nxt][mt][1], afr[nxt][mt][2], afr[nxt][mt][3],
                              aBase + aRow[mt] + koff[ks + 1]);
#pragma unroll
                    for (int np = 0; np < 4; np++)
                        LDMX4(bfr[nxt][np][0], bfr[nxt][np][1], bfr[nxt][np][2], bfr[nxt][np][3],
                              bBase + bRow[np] + koff[ks + 1]);
                }
                // all smem reads of this buffer are issued by end of ks=2:
                // release so next chunk's cp.async overlaps ks=2/ks=3 MMAs.
                if (ks == 2) __syncthreads();
#pragma unroll
                for (int mt = 0; mt < 4; mt++)
#pragma unroll
                    for (int nt = 0; nt < 8; nt++) {
                        int np = nt >> 1, hi = nt & 1;
                        MMA16816(acc[mt][nt], afr[cur][mt],
                                 bfr[cur][np][hi], bfr[cur][np][hi + 2]);
                    }
            }
        }

        // ---- epilogue: packed-key top-2 ----
        if (n0 + BN <= V) epilogue_topk<false>(acc, sc, colc, wm, l, n0, V, qidx);
        else              epilogue_topk<true >(acc, sc, colc, wm, l, n0, V, qidx);
        __syncthreads();

        // merge 8 partials per row; 128 threads, one row each
        {
            uint2 c0 = sc[0][tid];
            float h0 = __uint_as_float(c0.x), l0v = __uint_as_float(c0.y);
#pragma unroll
            for (int q = 1; q < 8; q++) {
                uint2 d = sc[q][tid];
                float bh = __uint_as_float(d.x), bl = __uint_as_float(d.y);
                float mn = fminf(h0, bh);
                h0  = fmaxf(h0, bh);
                l0v = fmaxf(mn, fmaxf(l0v, bl));
            }
            uint32_t k0 = __float_as_uint(h0), k1 = __float_as_uint(l0v);
            size_t base = ((size_t)(m0 + tid) * NC + bx) * 2;
            g_cval[base]     = __uint_as_float(k0 & 0xFFFFFF80u);
            g_cidx[base]     = n0 + (int)(k0 & 0x7Fu);
            g_cval[base + 1] = __uint_as_float(k1 & 0xFFFFFF80u);
            g_cidx[base + 1] = n0 + (int)(k1 & 0x7Fu);
        }
        __syncthreads();   // sc reads done before next tile's epilogue writes
    }
}

// ---------------- merge chunk candidates -> global top-2 per row ----------------
__global__ void reduce_topk_kernel(int NC) {
    __shared__ float sv0[256], sv1[256];
    __shared__ int   si0[256], si1[256];
    int b = blockIdx.x, t = threadIdx.x;
    int n = NC * 2;
    float v0 = NEGINF, v1 = NEGINF; int i0 = -1, i1 = -1;
    size_t base = (size_t)b * NC * 2;
    for (int j = t; j < n; j += 256) {
        float v = g_cval[base + j];
        int  id = g_cidx[base + j];
        if (v > v0)      { v1 = v0; i1 = i0; v0 = v; i0 = id; }
        else if (v > v1) { v1 = v;  i1 = id; }
    }
    sv0[t] = v0; sv1[t] = v1; si0[t] = i0; si1[t] = i1;
    __syncthreads();
    for (int s = 128; s > 0; s >>= 1) {
        if (t < s) {
            float bv0 = sv0[t+s], bv1 = sv1[t+s];
            int   bi0 = si0[t+s], bi1 = si1[t+s];
            float a0 = sv0[t], a1 = sv1[t];
            int   c0 = si0[t], c1 = si1[t];
            if (bv0 > a0) {
                a1 = a0; c1 = c0; a0 = bv0; c0 = bi0;
                if (bv1 > a1) { a1 = bv1; c1 = bi1; }
            } else if (bv0 > a1) { a1 = bv0; c1 = bi0; }
            sv0[t] = a0; sv1[t] = a1; si0[t] = c0; si1[t] = c1;
        }
        __syncthreads();
    }
    if (t == 0) { g_sel[b*2] = si0[0]; g_sel[b*2+1] = si1[0]; }
}

// ---------------- finalize: exact fp32 d_neg + hinge, atomic sum ----------------
__global__ void finalize_kernel(const float* __restrict__ in,
                                const float* __restrict__ tgt,
                                const float* __restrict__ vl,
                                float* __restrict__ out, int Brows) {
    __shared__ float sbuf[5][4];
    int b = blockIdx.x, t = threadIdx.x;   // 128 threads
    int s0 = g_sel[b*2], s1 = g_sel[b*2+1];
    const float4* ip  = (const float4*)(in  + (size_t)b  * D);
    const float4* tp  = (const float4*)(tgt + (size_t)b  * D);
    const float4* v0p = (const float4*)(vl  + (size_t)s0 * D);
    const float4* v1p = (const float4*)(vl  + (size_t)s1 * D);
    float4 iv = ip[t], tv = tp[t], a = v0p[t], c = v1p[t];

    float ii = iv.x*iv.x + iv.y*iv.y + iv.z*iv.z + iv.w*iv.w;
    float ia = iv.x*a.x  + iv.y*a.y  + iv.z*a.z  + iv.w*a.w;
    float aa = a.x*a.x   + a.y*a.y   + a.z*a.z   + a.w*a.w;
    float ic = iv.x*c.x  + iv.y*c.y  + iv.z*c.z  + iv.w*c.w;
    float cc = c.x*c.x   + c.y*c.y   + c.z*c.z   + c.w*c.w;
    int eq = (a.x == tv.x) && (a.y == tv.y) && (a.z == tv.z) && (a.w == tv.w);

    ii = warpSum(ii); ia = warpSum(ia); aa = warpSum(aa);
    ic = warpSum(ic); cc = warpSum(cc);
    int w = t >> 5, l = t & 31;
    if (l == 0) { sbuf[0][w]=ii; sbuf[1][w]=ia; sbuf[2][w]=aa; sbuf[3][w]=ic; sbuf[4][w]=cc; }
    int eq_all = __syncthreads_and(eq);
    if (t == 0) {
        float S[5];
#pragma unroll
        for (int qq = 0; qq < 5; qq++) S[qq] = sbuf[qq][0]+sbuf[qq][1]+sbuf[qq][2]+sbuf[qq][3];
        float ni = fmaxf(sqrtf(S[0]), EPS);
        float dotv, nn2;
        if (eq_all) { dotv = S[3]; nn2 = S[4]; }
        else        { dotv = S[1]; nn2 = S[2]; }
        float nv  = fmaxf(sqrtf(nn2), EPS);
        float sim = dotv / (ni * nv);
        float dneg = sqrtf(fmaxf(2.0f * (1.0f - sim), 1e-12f));
        float margin = 0.5f + g_dpos[b] - dneg;               // GAMMA + d_pos - d_neg
        float h = 2.0f * fmaxf(margin, 0.0f) / (float)Brows;  // RANK * hinge / B
        if (h != 0.0f) atomicAdd(out, h);
        else           atomicAdd(out, 0.0f);
    }
}

__global__ void zero_out_kernel(float* out, int n) {
    int i = blockIdx.x * blockDim.x + threadIdx.x;
    if (i < n) out[i] = 0.0f;
}

extern "C" void kernel_launch(void* const* d_in, const int* in_sizes, int n_in,
                              void* d_out, int out_size) {
    const float* in  = (const float*)d_in[0];
    const float* tgt = (const float*)d_in[1];
    const float* vl  = (const float*)d_in[2];
    float* out = (float*)d_out;

    int Brows = in_sizes[0] / D;      // 4096
    int V     = in_sizes[2] / D;      // 50000
    int NC    = (V + BN - 1) / BN;    // 391
    int NT    = (Brows / BM) * NC;    // 12512

    zero_out_kernel<<<(out_size + 127) / 128, 128>>>(out, out_size);
    prep_input_kernel<<<Brows, 128>>>(in, tgt);
    prep_vec_kernel<<<V, 128>>>(vl, V);

    static int smem_set = 0;
    if (!smem_set) {
        cudaFuncSetAttribute(gemm_hmma_kernel,
                             cudaFuncAttributeMaxDynamicSharedMemorySize, SMEM_BYTES);
        smem_set = 1;
    }
    gemm_hmma_kernel<<<296, 128, SMEM_BYTES>>>(V, NC, NT);

    reduce_topk_kernel<<<Brows, 256>>>(NC);
    finalize_kernel<<<Brows, 128>>>(in, tgt, vl, out, Brows);
}